// round 2
// baseline (speedup 1.0000x reference)
#include <cuda_runtime.h>
#include <cstdint>

#define D        32
#define D_ANCIL  16
#define DIN      80      // 2*D + D_ANCIL
#define HID      128
#define GRID_G   64
#define NN       4096    // GRID_G*GRID_G
#define BB       8
#define TOTAL    (BB*NN) // 32768
#define ROW      80      // floats per node row in (B,N,80)

// ---- packed f32x2 helpers (sm_100+ PTX; ptxas will not auto-fuse these) ----
#define FMA2(d, a, b, c) \
    asm("fma.rn.f32x2 %0, %1, %2, %3;" : "=l"(d) : "l"(a), "l"(b), "l"(c))
#define ADD2(d, a, b) \
    asm("add.rn.f32x2 %0, %1, %2;" : "=l"(d) : "l"(a), "l"(b))
#define PACK2(d, lo, hi) \
    asm("mov.b64 %0, {%1, %2};" : "=l"(d) : "f"(lo), "f"(hi))
#define UNPACK2(lo, hi, s) \
    asm("mov.b64 {%0, %1}, %2;" : "=f"(lo), "=f"(hi) : "l"(s))

__device__ __forceinline__ float tanh_fast(float x) {
    // tanh(x) = 1 - 2/(exp(2x)+1). __expf -> MUFU.EX2 (~2^-22 rel err).
    // Saturates correctly: exp->inf gives 1, exp->0 gives -1.
    float e = __expf(x + x);
    return 1.0f - __fdividef(2.0f, e + 1.0f);
}

// One half-update: z_tgt += dt_b * F(z_src, xi)  for all B*N nodes.
// state layout: (B, N, 80) rows = [q(32) | p(32) | xi(16)], float32.
__global__ void __launch_bounds__(128)
half_step_kernel(float* __restrict__ state,
                 const float* __restrict__ tfin,
                 const float* __restrict__ W1,   // (80,128) k-major, j contiguous
                 const float* __restrict__ b1,   // (128)
                 const float* __restrict__ W2,   // (128,32) j-major, d contiguous
                 const float* __restrict__ b2,   // (32)
                 int zoff, int toff,
                 float tstart, float dtmax)
{
    extern __shared__ __align__(16) float smem[];
    float* W1s = smem;              // [j][k] : 128*80
    float* W2s = W1s + HID * DIN;   // [j][d] : 128*32
    float* b1s = W2s + HID * D;     // [j]

    const int tid = threadIdx.x;

    // cooperative stage: W1 transposed into [j][k]
    for (int idx = tid; idx < HID * DIN; idx += 128) {
        int k = idx >> 7;           // 0..79
        int j = idx & 127;          // 0..127
        W1s[j * DIN + k] = W1[idx]; // coalesced global read
    }
    for (int idx = tid; idx < HID * D; idx += 128)
        W2s[idx] = W2[idx];
    if (tid < HID) b1s[tid] = b1[tid];

    const int g = blockIdx.x * 128 + tid;        // 0..32767
    const int b = g >> 12;                       // batch
    const int n = g & (NN - 1);                  // node
    const int r = n >> 6, c = n & (GRID_G - 1);
    const int nu = (((r + GRID_G - 1) & (GRID_G - 1)) << 6) | c;
    const int nd = (((r + 1) & (GRID_G - 1)) << 6) | c;
    const int nl = (r << 6) | ((c + GRID_G - 1) & (GRID_G - 1));
    const int nr = (r << 6) | ((c + 1) & (GRID_G - 1));

    const float* base = state + (size_t)b * NN * ROW;
    const float4* rowZ = (const float4*)(base + (size_t)n  * ROW + zoff);
    const float4* rowU = (const float4*)(base + (size_t)nu * ROW + zoff);
    const float4* rowD = (const float4*)(base + (size_t)nd * ROW + zoff);
    const float4* rowL = (const float4*)(base + (size_t)nl * ROW + zoff);
    const float4* rowR = (const float4*)(base + (size_t)nr * ROW + zoff);
    const float4* rowX = (const float4*)(base + (size_t)n  * ROW + 2 * D);

    // Pack input vector [z | mean(nbrs) | xi] directly into 40 f32x2 regs.
    unsigned long long xp[40];
    #pragma unroll
    for (int i = 0; i < 8; i++) {
        float4 o  = rowZ[i];
        float4 u  = rowU[i];
        float4 dn = rowD[i];
        float4 lf = rowL[i];
        float4 rt = rowR[i];
        float mx = 0.25f * (u.x + dn.x + lf.x + rt.x);
        float my = 0.25f * (u.y + dn.y + lf.y + rt.y);
        float mz = 0.25f * (u.z + dn.z + lf.z + rt.z);
        float mw = 0.25f * (u.w + dn.w + lf.w + rt.w);
        PACK2(xp[2 * i],      o.x, o.y);
        PACK2(xp[2 * i + 1],  o.z, o.w);
        PACK2(xp[16 + 2 * i],     mx, my);
        PACK2(xp[16 + 2 * i + 1], mz, mw);
    }
    #pragma unroll
    for (int i = 0; i < 4; i++) {
        float4 x = rowX[i];
        PACK2(xp[32 + 2 * i],     x.x, x.y);
        PACK2(xp[32 + 2 * i + 1], x.z, x.w);
    }

    // output accumulators (packed over d), init with b2
    unsigned long long oacc[16];
    {
        const float4* b2v = (const float4*)b2;
        #pragma unroll
        for (int i = 0; i < 8; i++) {
            float4 v = b2v[i];
            PACK2(oacc[2 * i],     v.x, v.y);
            PACK2(oacc[2 * i + 1], v.z, v.w);
        }
    }

    __syncthreads();

    #pragma unroll 2
    for (int j = 0; j < HID; j++) {
        const ulonglong2* wp =
            reinterpret_cast<const ulonglong2*>(W1s + j * DIN);
        unsigned long long a0 = 0ull, a1 = 0ull, a2 = 0ull, a3 = 0ull;
        // 80 floats = 40 f32x2 pairs = 20 ulonglong2 -> u = 0..18 step 2
        #pragma unroll
        for (int u = 0; u < 20; u += 2) {
            ulonglong2 w0 = wp[u];
            ulonglong2 w1 = wp[u + 1];
            FMA2(a0, xp[2 * u],     w0.x, a0);
            FMA2(a1, xp[2 * u + 1], w0.y, a1);
            FMA2(a2, xp[2 * u + 2], w1.x, a2);
            FMA2(a3, xp[2 * u + 3], w1.y, a3);
        }
        ADD2(a0, a0, a1);
        ADD2(a2, a2, a3);
        ADD2(a0, a0, a2);
        float slo, shi;
        UNPACK2(slo, shi, a0);
        float s = slo + shi + b1s[j];
        float t = tanh_fast(s);
        unsigned long long tt;
        PACK2(tt, t, t);

        const ulonglong2* w2p =
            reinterpret_cast<const ulonglong2*>(W2s + j * D);
        #pragma unroll
        for (int u = 0; u < 8; u++) {
            ulonglong2 w = w2p[u];
            FMA2(oacc[2 * u],     tt, w.x, oacc[2 * u]);
            FMA2(oacc[2 * u + 1], tt, w.y, oacc[2 * u + 1]);
        }
    }

    // dt = clip(tf - tstart, 0, dtmax), per batch (exact fp32 schedule)
    float tfv = tfin[b];
    float dtv = fminf(fmaxf(tfv - tstart, 0.0f), dtmax);

    float* tgt = state + (size_t)b * NN * ROW + (size_t)n * ROW + toff;
    #pragma unroll
    for (int u = 0; u < 8; u++) {
        float4 cur = *(float4*)(tgt + 4 * u);
        float o0, o1, o2, o3;
        UNPACK2(o0, o1, oacc[2 * u]);
        UNPACK2(o2, o3, oacc[2 * u + 1]);
        cur.x += dtv * o0;
        cur.y += dtv * o1;
        cur.z += dtv * o2;
        cur.w += dtv * o3;
        *(float4*)(tgt + 4 * u) = cur;
    }
}

extern "C" void kernel_launch(void* const* d_in, const int* in_sizes, int n_in,
                              void* d_out, int out_size)
{
    const float* x    = (const float*)d_in[0];
    const float* tf   = (const float*)d_in[1];
    const float* W1q  = (const float*)d_in[2];
    const float* b1q  = (const float*)d_in[3];
    const float* W2q  = (const float*)d_in[4];
    const float* b2q  = (const float*)d_in[5];
    const float* W1p  = (const float*)d_in[6];
    const float* b1p  = (const float*)d_in[7];
    const float* W2p  = (const float*)d_in[8];
    const float* b2p  = (const float*)d_in[9];
    float* state = (float*)d_out;

    const int smem = (HID * DIN + HID * D + HID) * (int)sizeof(float); // 57856 B
    cudaFuncSetAttribute(half_step_kernel,
                         cudaFuncAttributeMaxDynamicSharedMemorySize, smem);

    // state := x   (q,p,xi all copied; xi stays valid for the final output)
    cudaMemcpyAsync(state, x, (size_t)out_size * sizeof(float),
                    cudaMemcpyDeviceToDevice);

    const int blocks = TOTAL / 128; // 256
    const float DT = 0.25f;

    for (int k = 0; k < 18; k++) {
        // q-phase: reads p (zoff=32), writes q (toff=0)
        float tsq = (k == 0) ? 0.0f : (0.125f + (k - 1) * DT);
        float dmq = (k == 0) ? 0.125f : DT;
        half_step_kernel<<<blocks, 128, smem>>>(
            state, tf, W1q, b1q, W2q, b2q, /*zoff=*/D, /*toff=*/0, tsq, dmq);

        // p-phase: reads q (zoff=0), writes p (toff=32)
        float tsp = k * DT;
        half_step_kernel<<<blocks, 128, smem>>>(
            state, tf, W1p, b1p, W2p, b2p, /*zoff=*/0, /*toff=*/D, tsp, DT);
    }
    (void)in_sizes; (void)n_in;
}